// round 16
// baseline (speedup 1.0000x reference)
#include <cuda_runtime.h>
#include <cuda_fp16.h>
#include <math.h>
#include <stdint.h>

#define BV 2
#define LV 3073
#define EV 768
#define HH 12
#define DHv 64
#define ML (BV*LV)          // 6146 rows
#define NP 3072             // patches per batch
#define QKVS 2304           // fused qkv row stride
#define LOG2E 1.4426950408889634f

typedef __half fp16;

// ---------------- scratch (device globals) -----------------------------------
__device__ float g_h  [(size_t)ML*EV];
__device__ float g_hn [(size_t)ML*EV];
__device__ __align__(16) fp16 g_obr[(size_t)288*768*64];
__device__ float g_lse[(size_t)288*768];
__device__ float g_bqkv[2*QKVS];
__device__ __align__(16) fp16 g_col[(size_t)BV*NP*1024];
__device__ __align__(16) fp16 g_x  [(size_t)ML*EV];
__device__ __align__(16) fp16 g_qkv[(size_t)ML*QKVS];
__device__ __align__(16) fp16 g_m1 [(size_t)ML*3072];
__device__ __align__(16) fp16 g_o  [(size_t)ML*EV];
#define WTOT 14942208
__device__ __align__(16) fp16 g_wh[WTOT];
__device__ __align__(16) fp16 g_wl[WTOT];   // only patch region used (2-pass)

// ---------------- helpers -----------------------------------------------------
__device__ __forceinline__ float geluf(float v) {
    return 0.5f * v * (1.f + erff(v * 0.70710678118654752f));
}
__device__ __forceinline__ uint32_t s2u(const void* p) {
    uint32_t a;
    asm("{ .reg .u64 t; cvta.to.shared.u64 t, %1; cvt.u32.u64 %0, t; }" : "=r"(a) : "l"(p));
    return a;
}
__device__ __forceinline__ void cpa16(uint32_t saddr, const void* g, int sz) {
    asm volatile("cp.async.cg.shared.global [%0], [%1], 16, %2;"
                 :: "r"(saddr), "l"(g), "r"(sz) : "memory");
}
__device__ __forceinline__ void mma16816(float* d, const uint32_t* a, uint32_t b0, uint32_t b1) {
    asm volatile("mma.sync.aligned.m16n8k16.row.col.f32.f16.f16.f32 "
                 "{%0,%1,%2,%3},{%4,%5,%6,%7},{%8,%9},{%0,%1,%2,%3};"
                 : "+f"(d[0]), "+f"(d[1]), "+f"(d[2]), "+f"(d[3])
                 : "r"(a[0]), "r"(a[1]), "r"(a[2]), "r"(a[3]), "r"(b0), "r"(b1));
}
__device__ __forceinline__ void ldsm4(uint32_t& r0, uint32_t& r1, uint32_t& r2, uint32_t& r3,
                                      uint32_t saddr) {
    asm volatile("ldmatrix.sync.aligned.m8n8.x4.shared.b16 {%0,%1,%2,%3}, [%4];"
                 : "=r"(r0), "=r"(r1), "=r"(r2), "=r"(r3) : "r"(saddr));
}
__device__ __forceinline__ void ldsm4t(uint32_t& r0, uint32_t& r1, uint32_t& r2, uint32_t& r3,
                                       uint32_t saddr) {
    asm volatile("ldmatrix.sync.aligned.m8n8.x4.trans.shared.b16 {%0,%1,%2,%3}, [%4];"
                 : "=r"(r0), "=r"(r1), "=r"(r2), "=r"(r3) : "r"(saddr));
}
__device__ __forceinline__ uint32_t h2u(float c0, float c1) {
    __half2 h = __floats2half2_rn(c0, c1);
    return *(uint32_t*)&h;
}
__device__ __forceinline__ uint32_t ex2h2(float c0, float c1) {
    uint32_t x = h2u(c0, c1), r;
    asm("ex2.approx.f16x2 %0, %1;" : "=r"(r) : "r"(x));
    return r;
}

// ---------------- 2-pass fp16 GEMM, 128x128 tile (patch embed only) ----------
#define HG2_KCH 32
#define HG2_STR 40
#define HG2_MATH (128*HG2_STR)
#define HG2_BUFH (3*HG2_MATH)
#define HG2_SMEM (2*HG2_BUFH*2)

__global__ void __launch_bounds__(256, 2)
hgemm_patch(const fp16* __restrict__ A, const fp16* __restrict__ Bh, const fp16* __restrict__ Bl,
            const float* __restrict__ bias, const float* __restrict__ pos,
            float* __restrict__ C, int M, int N, int K)
{
    extern __shared__ fp16 sm[];
    const int tid = threadIdx.x, wid = tid >> 5, lane = tid & 31;
    const int m0 = blockIdx.x * 128, n0 = blockIdx.y * 128;
    const int g = lane >> 2, t = lane & 3;
    const int wm0 = (wid >> 1) * 32, wn0 = (wid & 1) * 64;
    const uint32_t smbase = s2u(sm);
    const fp16* srcs[3] = {A, Bh, Bl};
    const int arow8 = ((lane >> 3) & 1) * 8 + (lane & 7);
    const int acol8 = (lane >> 4) * 8;
    const int bnf   = lane >> 4;
    const int brow  = lane & 7;
    const int bcol8 = ((lane >> 3) & 1) * 8;

    float acc[2][8][4];
    #pragma unroll
    for (int i = 0; i < 2; ++i)
        #pragma unroll
        for (int j = 0; j < 8; ++j)
            #pragma unroll
            for (int u = 0; u < 4; ++u) acc[i][j][u] = 0.f;

    const int KC = K / HG2_KCH;

    auto issue = [&](int c) {
        int k0 = c * HG2_KCH;
        int buf = c & 1;
        #pragma unroll
        for (int mat = 0; mat < 3; ++mat) {
            #pragma unroll
            for (int it = 0; it < 2; ++it) {
                int idx = it * 256 + tid;
                int row = idx >> 2, q8 = idx & 3;
                int grow = (mat == 0) ? (m0 + row) : (n0 + row);
                bool ok = (mat > 0) || (grow < M);
                const fp16* gp = ok ? (srcs[mat] + (size_t)grow * K + k0 + q8 * 8) : srcs[mat];
                uint32_t sa = smbase + (uint32_t)(buf * HG2_BUFH + mat * HG2_MATH + row * HG2_STR + q8 * 8) * 2;
                cpa16(sa, gp, ok ? 16 : 0);
            }
        }
        asm volatile("cp.async.commit_group;" ::: "memory");
    };

    issue(0);
    for (int c = 0; c < KC; ++c) {
        if (c + 1 < KC) {
            issue(c + 1);
            asm volatile("cp.async.wait_group 1;" ::: "memory");
        } else {
            asm volatile("cp.async.wait_group 0;" ::: "memory");
        }
        __syncthreads();
        const uint32_t bufoff = (uint32_t)(c & 1) * HG2_BUFH;
        #pragma unroll
        for (int ks = 0; ks < HG2_KCH; ks += 16) {
            uint32_t afr[2][4];
            #pragma unroll
            for (int mf = 0; mf < 2; ++mf) {
                uint32_t addr = smbase + (bufoff + (uint32_t)((wm0 + mf * 16 + arow8) * HG2_STR + ks + acol8)) * 2;
                ldsm4(afr[mf][0], afr[mf][1], afr[mf][2], afr[mf][3], addr);
            }
            #pragma unroll
            for (int p = 0; p < 8; p += 2) {
                uint32_t b0, b1, b2, b3, l0, l1, l2, l3;
                uint32_t baddr = smbase + (bufoff + (uint32_t)(HG2_MATH + (wn0 + (p + bnf) * 8 + brow) * HG2_STR + ks + bcol8)) * 2;
                ldsm4(b0, b1, b2, b3, baddr);
                ldsm4(l0, l1, l2, l3, baddr + HG2_MATH * 2);
                #pragma unroll
                for (int mf = 0; mf < 2; ++mf) {
                    mma16816(acc[mf][p],     afr[mf], b0, b1);
                    mma16816(acc[mf][p + 1], afr[mf], b2, b3);
                    mma16816(acc[mf][p],     afr[mf], l0, l1);
                    mma16816(acc[mf][p + 1], afr[mf], l2, l3);
                }
            }
        }
        __syncthreads();
    }

    #pragma unroll
    for (int mf = 0; mf < 2; ++mf) {
        #pragma unroll
        for (int rr = 0; rr < 2; ++rr) {
            int row = m0 + wm0 + mf * 16 + g + rr * 8;
            if (row >= M) continue;
            int bI = row / NP, pI = row - bI * NP;
            size_t hrow = (size_t)bI * LV + 1 + pI;
            #pragma unroll
            for (int nf = 0; nf < 8; ++nf) {
                int col = n0 + wn0 + nf * 8 + 2 * t;
                float c0 = acc[mf][nf][rr * 2 + 0] + bias[col] + pos[(size_t)(1 + pI) * EV + col];
                float c1 = acc[mf][nf][rr * 2 + 1] + bias[col + 1] + pos[(size_t)(1 + pI) * EV + col + 1];
                *(float2*)(C + hrow * EV + col) = make_float2(c0, c1);
            }
        }
    }
}

// ---------------- 1-pass fp16 GEMM, 256x128 tile, 512 threads -----------------
#define BG_KCH 64
#define BG_STR 72
#define BG_AMAT (256*BG_STR)
#define BG_BMAT (128*BG_STR)
#define BG_BUFH (BG_AMAT + BG_BMAT)
#define BG_SMEM (2*BG_BUFH*2)

template<int ACT, int OUT, int QSCALE>
__global__ void __launch_bounds__(512, 1)
hgemm_big(const fp16* __restrict__ A, const fp16* __restrict__ Bh,
          const float* __restrict__ bias, const float* __restrict__ res,
          float* __restrict__ C, fp16* __restrict__ Cf, int M, int N, int K)
{
    extern __shared__ fp16 sm[];
    const int tid = threadIdx.x, wid = tid >> 5, lane = tid & 31;
    const int m0 = blockIdx.x * 256, n0 = blockIdx.y * 128;
    const int g = lane >> 2, t = lane & 3;
    const int wm0 = (wid >> 1) * 32, wn0 = (wid & 1) * 64;
    const uint32_t smbase = s2u(sm);
    const int arow8 = ((lane >> 3) & 1) * 8 + (lane & 7);
    const int acol8 = (lane >> 4) * 8;
    const int bnf   = lane >> 4;
    const int brow  = lane & 7;
    const int bcol8 = ((lane >> 3) & 1) * 8;

    float acc[2][8][4];
    #pragma unroll
    for (int i = 0; i < 2; ++i)
        #pragma unroll
        for (int j = 0; j < 8; ++j)
            #pragma unroll
            for (int u = 0; u < 4; ++u) acc[i][j][u] = 0.f;

    const int KC = K / BG_KCH;

    auto issue = [&](int c) {
        int k0 = c * BG_KCH;
        int buf = c & 1;
        // A: 256 rows x 8 groups = 2048 cp / 512 thr = 4 iters
        #pragma unroll
        for (int it = 0; it < 4; ++it) {
            int idx = it * 512 + tid;
            int row = idx >> 3, q8 = idx & 7;
            int grow = m0 + row;
            bool ok = grow < M;
            const fp16* gp = ok ? (A + (size_t)grow * K + k0 + q8 * 8) : A;
            uint32_t sa = smbase + (uint32_t)(buf * BG_BUFH + row * BG_STR + q8 * 8) * 2;
            cpa16(sa, gp, ok ? 16 : 0);
        }
        // B: 128 rows x 8 groups = 1024 cp / 512 thr = 2 iters
        #pragma unroll
        for (int it = 0; it < 2; ++it) {
            int idx = it * 512 + tid;
            int row = idx >> 3, q8 = idx & 7;
            const fp16* gp = Bh + (size_t)(n0 + row) * K + k0 + q8 * 8;
            uint32_t sa = smbase + (uint32_t)(buf * BG_BUFH + BG_AMAT + row * BG_STR + q8 * 8) * 2;
            cpa16(sa, gp, 16);
        }
        asm volatile("cp.async.commit_group;" ::: "memory");
    };

    issue(0);
    for (int c = 0; c < KC; ++c) {
        if (c + 1 < KC) {
            issue(c + 1);
            asm volatile("cp.async.wait_group 1;" ::: "memory");
        } else {
            asm volatile("cp.async.wait_group 0;" ::: "memory");
        }
        __syncthreads();
        const uint32_t bufoff = (uint32_t)(c & 1) * BG_BUFH;
        #pragma unroll
        for (int ks = 0; ks < BG_KCH; ks += 16) {
            uint32_t afr[2][4];
            #pragma unroll
            for (int mf = 0; mf < 2; ++mf) {
                uint32_t addr = smbase + (bufoff + (uint32_t)((wm0 + mf * 16 + arow8) * BG_STR + ks + acol8)) * 2;
                ldsm4(afr[mf][0], afr[mf][1], afr[mf][2], afr[mf][3], addr);
            }
            #pragma unroll
            for (int p = 0; p < 8; p += 2) {
                uint32_t b0, b1, b2, b3;
                uint32_t baddr = smbase + (bufoff + (uint32_t)(BG_AMAT + (wn0 + (p + bnf) * 8 + brow) * BG_STR + ks + bcol8)) * 2;
                ldsm4(b0, b1, b2, b3, baddr);
                #pragma unroll
                for (int mf = 0; mf < 2; ++mf) {
                    mma16816(acc[mf][p],     afr[mf], b0, b1);
                    mma16816(acc[mf][p + 1], afr[mf], b2, b3);
                }
            }
        }
        __syncthreads();
    }

    #pragma unroll
    for (int mf = 0; mf < 2; ++mf) {
        #pragma unroll
        for (int rr = 0; rr < 2; ++rr) {
            int row = m0 + wm0 + mf * 16 + g + rr * 8;
            if (row >= M) continue;
            #pragma unroll
            for (int nf = 0; nf < 8; ++nf) {
                int col = n0 + wn0 + nf * 8 + 2 * t;
                float c0 = acc[mf][nf][rr * 2 + 0] + bias[col];
                float c1 = acc[mf][nf][rr * 2 + 1] + bias[col + 1];
                if (ACT) { c0 = geluf(c0); c1 = geluf(c1); }
                if (QSCALE && col < 768) { c0 *= 0.125f; c1 *= 0.125f; }
                if (OUT == 1) {
                    __half2 h = __floats2half2_rn(c0, c1);
                    *(__half2*)(Cf + (size_t)row * N + col) = h;
                } else {
                    if (res) {
                        c0 += res[(size_t)row * N + col];
                        c1 += res[(size_t)row * N + col + 1];
                    }
                    *(float2*)(C + (size_t)row * N + col) = make_float2(c0, c1);
                }
            }
        }
    }
}

// ---------------- fused flash attention — 64-key chunks, occupancy 2 ---------
#define FA_STR 72
#define FA_Q 0
#define FA_K(b)  (9216 + (b)*4608)
#define FA_V(b)  (18432 + (b)*4608)
#define FA_SMEM (27648*2)

__global__ void __launch_bounds__(256, 2)
fattn(const fp16* __restrict__ qkv, int layer_unused)
{
    const int wsA[5] = {768, 1536, 3072, 6144, 12288};
    const int rsA[5] = {1, 2, 4, 8, 16};
    const int gsA[5] = {12, 6, 3, 2, 1};
    const int nsA[5] = {5, 3, 2, 1, 1};
    const int ubA[5] = {0, 120, 192, 240, 264};

    extern __shared__ fp16 sm[];
    const int tid = threadIdx.x, wid = tid >> 5, lane = tid & 31;
    const int g = lane >> 2, t = lane & 3;
    int gu = blockIdx.y;
    int br = (gu >= 264) ? 4 : (gu >= 240) ? 3 : (gu >= 192) ? 2 : (gu >= 120) ? 1 : 0;
    int z = gu - ubA[br];
    int w = wsA[br], r = rsA[br], gsz = gsA[br], n = nsA[br];
    int hd = z % HH;
    int seg = (z / HH) % n;
    int bb_ = z / (HH * n);
    int off = hd / gsz;
    int m0 = blockIdx.x * 128;
    const uint32_t smb = s2u(sm);
    const int arow8 = ((lane >> 3) & 1) * 8 + (lane & 7);
    const int acol8 = (lane >> 4) * 8;
    const int bnf   = lane >> 4;
    const int brow  = lane & 7;
    const int bcol8 = ((lane >> 3) & 1) * 8;
    const int vrow  = lane & 15;
    const int vcol  = lane >> 4;
    const fp16* q = qkv;
    const fp16* k = qkv + 768;
    const fp16* v = qkv + 1536;

    auto kv_issue = [&](int kt, int buf) {
        int n0 = kt * 64;
        #pragma unroll
        for (int it = 0; it < 2; ++it) {
            int idx = it * 256 + tid;
            int row = idx >> 3, q8 = idx & 7;
            int pos = seg * w + (n0 + row) * r + off;
            bool ok = pos < LV;
            const fp16* gpk = ok ? (k + ((size_t)(bb_ * LV) + pos) * QKVS + hd * DHv + q8 * 8) : k;
            cpa16(smb + (uint32_t)(FA_K(buf) + row * FA_STR + q8 * 8) * 2, gpk, ok ? 16 : 0);
            const fp16* gpv = ok ? (v + ((size_t)(bb_ * LV) + pos) * QKVS + hd * DHv + q8 * 8) : v;
            cpa16(smb + (uint32_t)(FA_V(buf) + row * FA_STR + q8 * 8) * 2, gpv, ok ? 16 : 0);
        }
        asm volatile("cp.async.commit_group;" ::: "memory");
    };

    #pragma unroll
    for (int it = 0; it < 4; ++it) {
        int idx = it * 256 + tid;
        int row = idx >> 3, q8 = idx & 7;
        int pos = seg * w + (m0 + row) * r + off;
        bool ok = pos < LV;
        const fp16* gp = ok ? (q + ((size_t)(bb_ * LV) + pos) * QKVS + hd * DHv + q8 * 8) : q;
        cpa16(smb + (uint32_t)(FA_Q + row * FA_STR + q8 * 8) * 2, gp, ok ? 16 : 0);
    }
    kv_issue(0, 0);
    asm volatile("cp.async.wait_group 0;" ::: "memory");
    __syncthreads();

    uint32_t qfr[4][4];
    #pragma unroll
    for (int k4 = 0; k4 < 4; ++k4) {
        uint32_t addr = smb + (uint32_t)(FA_Q + (wid * 16 + arow8) * FA_STR + k4 * 16 + acol8) * 2;
        ldsm4(qfr[k4][0], qfr[k4][1], qfr[k4][2], qfr[k4][3], addr);
    }

    float m_[2] = {-1e30f, -1e30f};
    float l_[2] = {0.f, 0.f};
    float acco[8][4];
    #pragma unroll
    for (int j = 0; j < 8; ++j)
        #pragma unroll
        for (int u = 0; u < 4; ++u) acco[j][u] = 0.f;

    for (int kt = 0; kt < 12; ++kt) {
        int buf = kt & 1;
        if (kt < 11) kv_issue(kt + 1, buf ^ 1);

        float accs[8][4];
        #pragma unroll
        for (int j = 0; j < 8; ++j)
            #pragma unroll
            for (int u = 0; u < 4; ++u) accs[j][u] = 0.f;
        #pragma unroll
        for (int k4 = 0; k4 < 4; ++k4) {
            #pragma unroll
            for (int p = 0; p < 8; p += 2) {
                uint32_t b0, b1, b2, b3;
                uint32_t addr = smb + (uint32_t)(FA_K(buf) + ((p + bnf) * 8 + brow) * FA_STR + k4 * 16 + bcol8) * 2;
                ldsm4(b0, b1, b2, b3, addr);
                mma16816(accs[p],     qfr[k4], b0, b1);
                mma16816(accs[p + 1], qfr[k4], b2, b3);
            }
        }

        float mx0 = -1e30f, mx1 = -1e30f;
        #pragma unroll
        for (int nf = 0; nf < 8; ++nf) {
            mx0 = fmaxf(mx0, fmaxf(accs[nf][0], accs[nf][1]));
            mx1 = fmaxf(mx1, fmaxf(accs[nf][2], accs[nf][3]));
        }
        mx0 = fmaxf(mx0, __shfl_xor_sync(0xffffffffu, mx0, 1));
        mx0 = fmaxf(mx0, __shfl_xor_sync(0xffffffffu, mx0, 2));
        mx1 = fmaxf(mx1, __shfl_xor_sync(0xffffffffu, mx1, 1));
        mx1 = fmaxf(mx1, __shfl_xor_sync(0xffffffffu, mx1, 2));
        float mn0 = fmaxf(m_[0], mx0), mn1 = fmaxf(m_[1], mx1);
        float mnl0 = mn0 * LOG2E, mnl1 = mn1 * LOG2E;
        uint32_t pfr[8][2];
        float sum0 = 0.f, sum1 = 0.f;
        #pragma unroll
        for (int nf = 0; nf < 8; ++nf) {
            float t0 = fmaf(accs[nf][0], LOG2E, -mnl0);
            float t1 = fmaf(accs[nf][1], LOG2E, -mnl0);
            float t2 = fmaf(accs[nf][2], LOG2E, -mnl1);
            float t3 = fmaf(accs[nf][3], LOG2E, -mnl1);
            pfr[nf][0] = ex2h2(t0, t1);
            pfr[nf][1] = ex2h2(t2, t3);
            float2 f0 = __half22float2(*(__half2*)&pfr[nf][0]);
            float2 f1 = __half22float2(*(__half2*)&pfr[nf][1]);
            sum0 += f0.x + f0.y;
            sum1 += f1.x + f1.y;
        }
        sum0 += __shfl_xor_sync(0xffffffffu, sum0, 1);
        sum0 += __shfl_xor_sync(0xffffffffu, sum0, 2);
        sum1 += __shfl_xor_sync(0xffffffffu, sum1, 1);
        sum1 += __shfl_xor_sync(0xffffffffu, sum1, 2);
        float sc0 = __expf(m_[0] - mn0), sc1 = __expf(m_[1] - mn1);
        l_[0] = l_[0] * sc0 + sum0;
        l_[1] = l_[1] * sc1 + sum1;
        m_[0] = mn0; m_[1] = mn1;
        #pragma unroll
        for (int nf = 0; nf < 8; ++nf) {
            acco[nf][0] *= sc0; acco[nf][1] *= sc0;
            acco[nf][2] *= sc1; acco[nf][3] *= sc1;
        }

        #pragma unroll
        for (int kb = 0; kb < 4; ++kb) {
            uint32_t a[4] = {pfr[2*kb][0], pfr[2*kb][1], pfr[2*kb+1][0], pfr[2*kb+1][1]};
            #pragma unroll
            for (int p = 0; p < 8; p += 2) {
                uint32_t b0, b1, b2, b3;
                uint32_t addr = smb + (uint32_t)(FA_V(buf) + (kb * 16 + vrow) * FA_STR + (p + vcol) * 8) * 2;
                ldsm4t(b0, b1, b2, b3, addr);
                mma16816(acco[p],     a, b0, b1);
                mma16816(acco[p + 1], a, b2, b3);
            }
        }

        if (kt < 11) {
            asm volatile("cp.async.wait_group 0;" ::: "memory");
            __syncthreads();
        }
    }

    float inv0 = 1.f / l_[0], inv1 = 1.f / l_[1];
    int row0 = m0 + wid * 16 + g;
    int row1 = row0 + 8;
    fp16* Op = g_obr + (size_t)gu * 49152;
    #pragma unroll
    for (int nf = 0; nf < 8; ++nf) {
        int col = nf * 8 + 2 * t;
        *(__half2*)(Op + (size_t)row0 * 64 + col) = __floats2half2_rn(acco[nf][0] * inv0, acco[nf][1] * inv0);
        *(__half2*)(Op + (size_t)row1 * 64 + col) = __floats2half2_rn(acco[nf][2] * inv1, acco[nf][3] * inv1);
    }
    if (t == 0) {
        g_lse[(size_t)gu * 768 + row0] = m_[0] + logf(l_[0]);
        g_lse[(size_t)gu * 768 + row1] = m_[1] + logf(l_[1]);
    }
}

// ---------------- misc kernels ------------------------------------------------
__global__ void im2col_half(const float* __restrict__ x) {
    int idx = blockIdx.x * 256 + threadIdx.x;
    if (idx >= BV * NP * 1024) return;
    int kk = idx & 1023;
    int p  = (idx >> 10) % NP;
    int b  = (idx >> 10) / NP;
    int pw_ = kk & 15, ph_ = (kk >> 4) & 15, pd_ = kk >> 8;
    int bz = p & 15, by = (p >> 4) & 15, bx = p >> 8;
    float v = x[(((size_t)b * 48 + bx * 4 + pd_) * 256 + by * 16 + ph_) * 256 + bz * 16 + pw_];
    g_col[idx] = __float2half_rn(v);
}

__global__ void cls_kernel(const float* __restrict__ cls, const float* __restrict__ pos) {
    int e = blockIdx.x * 256 + threadIdx.x;
    if (e >= EV) return;
    float v = cls[e] + pos[e];
    g_h[e] = v;
    g_h[(size_t)LV * EV + e] = v;
}

template<int HOUT>
__global__ void layernorm_kernel(const float* __restrict__ x, const float* __restrict__ g,
                                 const float* __restrict__ bta, float* __restrict__ y,
                                 fp16* __restrict__ yf)
{
    int row = blockIdx.x * 8 + (threadIdx.x >> 5);
    if (row >= ML) return;
    int lane = threadIdx.x & 31;
    const float4* xr = (const float4*)(x + (size_t)row * EV);
    float4 v[6];
    float s = 0.f, s2 = 0.f;
    #pragma unroll
    for (int i = 0; i < 6; ++i) {
        v[i] = xr[lane + 32 * i];
        s  += v[i].x + v[i].y + v[i].z + v[i].w;
        s2 += v[i].x*v[i].x + v[i].y*v[i].y + v[i].z*v[i].z + v[i].w*v[i].w;
    }
    #pragma unroll
    for (int o = 16; o; o >>= 1) {
        s  += __shfl_xor_sync(0xffffffffu, s, o);
        s2 += __shfl_xor_sync(0xffffffffu, s2, o);
    }
    float mu = s * (1.f / 768.f);
    float var = s2 * (1.f / 768.f) - mu * mu;
    float inv = rsqrtf(var + 1e-5f);
    #pragma unroll
    for (int i = 0; i < 6; ++i) {
        int j = lane + 32 * i;
        float4 gg = ((const float4*)g)[j];
        float4 bb = ((const float4*)bta)[j];
        float c0 = (v[i].x - mu) * inv * gg.x + bb.x;
        float c1 = (v[i].y - mu) * inv * gg.y + bb.y;
        float c2 = (v[i].z - mu) * inv * gg.z + bb.z;
        float c3 = (v[i].w - mu) * inv * gg.w + bb.w;
        if (HOUT) {
            __half2* yp = (__half2*)(yf + (size_t)row * EV + 4 * j);
            yp[0] = __floats2half2_rn(c0, c1);
            yp[1] = __floats2half2_rn(c2, c3);
        } else {
            ((float4*)(y + (size_t)row * EV))[j] = make_float4(c0, c1, c2, c3);
        }
    }
}

__global__ void combine_kernel()
{
    int idx = blockIdx.x * 4 + (threadIdx.x >> 6);
    int d = threadIdx.x & 63;
    int hd = idx % HH;
    int p = (idx / HH) % LV;
    int b = idx / (HH * LV);
    if (b >= BV) return;
    const int ws[5] = {768, 1536, 3072, 6144, 12288};
    const int rs[5] = {1, 2, 4, 8, 16};
    const int gs[5] = {12, 6, 3, 2, 1};
    const int ns[5] = {5, 3, 2, 1, 1};
    const int ub[5] = {0, 120, 192, 240, 264};
    float lses[5];
    size_t oix[5];
    bool cov[5];
    float mx = -1e30f;
    #pragma unroll
    for (int br = 0; br < 5; ++br) {
        int seg = p / ws[br];
        int jj = p - seg * ws[br];
        int off = hd / gs[br];
        int rr = jj & (rs[br] - 1);
        cov[br] = (rr == off);
        if (cov[br]) {
            int j = jj / rs[br];
            int unit = ub[br] + (b * ns[br] + seg) * HH + hd;
            lses[br] = g_lse[(size_t)unit * 768 + j];
            oix[br] = (size_t)unit * 49152 + (size_t)j * 64;
            mx = fmaxf(mx, lses[br]);
        }
    }
    float sw = 0.f, out = 0.f;
    #pragma unroll
    for (int br = 0; br < 5; ++br) {
        if (cov[br]) {
            float wgt = __expf(lses[br] - mx);
            sw += wgt;
            out += wgt * __half2float(g_obr[oix[br] + d]);
        }
    }
    g_o[((size_t)(b * LV + p)) * EV + hd * DHv + d] = __float2half_rn(out / sw);
}

__global__ void head_kernel(const float* __restrict__ hn, const float* __restrict__ W,
                            const float* __restrict__ bias, float* __restrict__ out)
{
    int nidx = blockIdx.x * blockDim.x + threadIdx.x;
    int b = blockIdx.y;
    if (nidx >= 1000) return;
    const float* row = hn + (size_t)b * LV * EV;
    float acc = bias[nidx];
    for (int e = 0; e < EV; ++e) acc = fmaf(row[e], W[(size_t)e * 1000 + nidx], acc);
    out[b * 1000 + nidx] = acc;
}

__global__ void transT_all(const float* __restrict__ wq, const float* __restrict__ wk,
                           const float* __restrict__ wv, const float* __restrict__ wo,
                           const float* __restrict__ w1, const float* __restrict__ w2,
                           fp16* __restrict__ dst)
{
    int tile = blockIdx.x;
    const float* src;
    int K, N, kb, nb;
    size_t doff;
    if (tile < 2304) {
        int wsel = tile / 576, tt = tile % 576;
        src = (wsel == 0) ? wq : (wsel == 1) ? wk : (wsel == 2) ? wv : wo;
        K = 768; N = 768; doff = (size_t)wsel * 589824;
        kb = (tt % 24) * 32; nb = (tt / 24) * 32;
    } else if (tile < 4608) {
        int tt = tile - 2304;
        src = w1; K = 768; N = 3072; doff = 2359296;
        kb = (tt % 24) * 32; nb = (tt / 24) * 32;
    } else {
        int tt = tile - 4608;
        src = w2; K = 3072; N = 768; doff = 4718592;
        kb = (tt % 96) * 32; nb = (tt / 96) * 32;
    }
    __shared__ float t[32][33];
    int x = threadIdx.x, y = threadIdx.y;
    #pragma unroll
    for (int i = 0; i < 32; i += 8)
        t[y + i][x] = src[(size_t)(kb + y + i) * N + nb + x];
    __syncthreads();
    #pragma unroll
    for (int i = 0; i < 32; i += 8)
        dst[doff + (size_t)(nb + y + i) * K + kb + x] = __float2half_rn(t[x][y + i]);
}

__global__ void split_copy(const float* __restrict__ s, fp16* __restrict__ oh,
                           fp16* __restrict__ ol, long n)
{
    long i = ((long)blockIdx.x * 256 + threadIdx.x) * 4;
    if (i >= n) return;
    float4 v = *(const float4*)(s + i);
    float vv[4] = {v.x, v.y, v.z, v.w};
    #pragma unroll
    for (int u = 0; u < 4; ++u) {
        fp16 h = __float2half_rn(vv[u]);
        oh[i + u] = h;
        ol[i + u] = __float2half_rn(vv[u] - __half2float(h));
    }
}

__global__ void pack_bias(const float* __restrict__ bq, const float* __restrict__ bk,
                          const float* __restrict__ bv)
{
    int i = blockIdx.x * 256 + threadIdx.x;
    if (i >= 2 * QKVS) return;
    int l = i / QKVS, e = i % QKVS;
    float v;
    if (e < 768)       v = bq[l * EV + e];
    else if (e < 1536) v = bk[l * EV + e - 768];
    else               v = bv[l * EV + e - 1536];
    g_bqkv[i] = v;
}

// ---------------- host orchestration ------------------------------------------
extern "C" void kernel_launch(void* const* d_in, const int* in_sizes, int n_in,
                              void* d_out, int out_size)
{
    (void)in_sizes; (void)n_in; (void)out_size;
    const float* x        = (const float*)d_in[0];
    const float* patch_w  = (const float*)d_in[1];
    const float* patch_b  = (const float*)d_in[2];
    const float* cls_tok  = (const float*)d_in[3];
    const float* pos_emb  = (const float*)d_in[4];
    const float* ln1_g    = (const float*)d_in[5];
    const float* ln1_b    = (const float*)d_in[6];
    const float* wq       = (const float*)d_in[7];
    const float* bq       = (const float*)d_in[8];
    const float* wk       = (const float*)d_in[9];
    const float* bk       = (const float*)d_in[10];
    const float* wv       = (const float*)d_in[11];
    const float* bv_      = (const float*)d_in[12];
    const float* wo       = (const float*)d_in[13];
    const float* bo       = (const float*)d_in[14];
    const float* ln2_g    = (const float*)d_in[15];
    const float* ln2_b    = (const float*)d_in[16];
    const float* w1       = (const float*)d_in[17];
    const float* b1       = (const float*)d_in[18];
    const float* w2       = (const float*)d_in[19];
    const float* b2       = (const float*)d_in[20];
    const float* normf_g  = (const float*)d_in[21];
    const float* normf_b  = (const float*)d_in[22];
    const float* head_w   = (const float*)d_in[23];
    const float* head_b   = (const float*)d_in[24];
    float* out = (float*)d_out;

    float *p_h, *p_hn, *p_bqkv;
    fp16 *p_col, *p_x, *p_qkv, *p_m1, *p_o, *p_wh, *p_wl;
    cudaGetSymbolAddress((void**)&p_h, g_h);
    cudaGetSymbolAddress((void**)&p_hn, g_hn);
    cudaGetSymbolAddress((void**)&p_bqkv, g_bqkv);
    cudaGetSymbolAddress((void**)&p_col, g_col);
    cudaGetSymbolAddress((void**)&p_x, g_x);
    cudaGetSymbolAddress((void**)&p_qkv, g_qkv);
    cudaGetSymbolAddress((void**)&p_m1, g_m1);
    cudaGetSymbolAddress((void**)&p_o, g_o);
    cudaGetSymbolAddress((void**)&p_wh, g_wh);
    cudaGetSymbolAddress((void**)&p_wl, g_wl);

    cudaFuncSetAttribute(hgemm_patch, cudaFuncAttributeMaxDynamicSharedMemorySize, HG2_SMEM);
    cudaFuncSetAttribute(hgemm_big<0,1,1>, cudaFuncAttributeMaxDynamicSharedMemorySize, BG_SMEM);
    cudaFuncSetAttribute(hgemm_big<0,0,0>, cudaFuncAttributeMaxDynamicSharedMemorySize, BG_SMEM);
    cudaFuncSetAttribute(hgemm_big<1,1,0>, cudaFuncAttributeMaxDynamicSharedMemorySize, BG_SMEM);
    cudaFuncSetAttribute(fattn, cudaFuncAttributeMaxDynamicSharedMemorySize, FA_SMEM);

    // ---- prep (launch #5 = patch hgemm, for ncu capture) -----------------------
    const size_t LSZ = 7077888;
    dim3 blk(32, 8);
    {
        long n = 786432;
        split_copy<<<(int)((n/4 + 255) / 256), 256>>>(patch_w, p_wh, p_wl, n);       // 1
    }
    im2col_half<<<(BV * NP * 1024 + 255) / 256, 256>>>(x);                           // 2
    pack_bias<<<(2 * QKVS + 255) / 256, 256>>>(bq, bk, bv_);                         // 3
    transT_all<<<6912, blk>>>(wq, wk, wv, wo, w1, w2, p_wh + 786432);                // 4
    hgemm_patch<<<dim3(48, 6), 256, HG2_SMEM>>>(p_col, p_wh, p_wl,
                                                patch_b, pos_emb, p_h,
                                                BV * NP, EV, 1024);                  // 5 <- profiled
    transT_all<<<6912, blk>>>(wq + 589824, wk + 589824, wv + 589824, wo + 589824,
                              w1 + 2359296, w2 + 2359296, p_wh + 786432 + LSZ);      // 6
    cls_kernel<<<3, 256>>>(cls_tok, pos_emb);

    dim3 gEEb(25, 6);     // ceil(6146/256) x N/128
    dim3 gQKVb(25, 18);
    dim3 gE4b(25, 24);
    const int LNG = (ML + 7) / 8;

    for (int layer = 0; layer < 2; ++layer) {
        size_t base = 786432 + (size_t)layer * LSZ;
        size_t oE  = (size_t)layer * EV;
        size_t o4  = (size_t)layer * 3072;

        layernorm_kernel<1><<<LNG, 256>>>(p_h, ln1_g + oE, ln1_b + oE, nullptr, p_x);
        hgemm_big<0,1,1><<<gQKVb, 512, BG_SMEM>>>(p_x, p_wh + base,
                                                  p_bqkv + layer * QKVS, nullptr, nullptr, p_qkv,
                                                  ML, QKVS, EV);

        fattn<<<dim3(6, 288), 256, FA_SMEM>>>(p_qkv, layer);
        combine_kernel<<<(BV * LV * HH + 3) / 4, 256>>>();

        hgemm_big<0,0,0><<<gEEb, 512, BG_SMEM>>>(p_o, p_wh + base + 1769472, bo + oE, p_h, p_h, nullptr, ML, EV, EV);

        layernorm_kernel<1><<<LNG, 256>>>(p_h, ln2_g + oE, ln2_b + oE, nullptr, p_x);
        hgemm_big<1,1,0><<<gE4b, 512, BG_SMEM>>>(p_x, p_wh + base + 2359296, b1 + o4, nullptr, nullptr, p_m1, ML, 3072, EV);
        hgemm_big<0,0,0><<<gEEb, 512, BG_SMEM>>>(p_m1, p_wh + base + 4718592, b2 + oE, p_h, p_h, nullptr, ML, EV, 3072);
    }

    layernorm_kernel<0><<<LNG, 256>>>(p_h, normf_g, normf_b, p_hn, nullptr);
    head_kernel<<<dim3(4, BV), 256>>>(p_hn, head_w, head_b, out);
}

// round 17
// speedup vs baseline: 1.0484x; 1.0484x over previous
#include <cuda_runtime.h>
#include <cuda_fp16.h>
#include <math.h>
#include <stdint.h>

#define BV 2
#define LV 3073
#define EV 768
#define HH 12
#define DHv 64
#define ML (BV*LV)          // 6146 rows
#define NP 3072             // patches per batch
#define QKVS 2304           // fused qkv row stride
#define LOG2E 1.4426950408889634f

typedef __half fp16;

// ---------------- scratch (device globals) -----------------------------------
__device__ float g_h  [(size_t)ML*EV];
__device__ float g_hn [(size_t)BV*EV];          // only cls rows needed
__device__ __align__(16) fp16 g_obr[(size_t)288*768*64];
__device__ float g_lse[(size_t)288*768];
__device__ float g_bqkv[2*QKVS];
__device__ __align__(16) fp16 g_col[(size_t)BV*NP*1024];
__device__ __align__(16) fp16 g_x  [(size_t)ML*EV];
__device__ __align__(16) fp16 g_qkv[(size_t)ML*QKVS];
__device__ __align__(16) fp16 g_m1 [(size_t)ML*3072];
__device__ __align__(16) fp16 g_o  [(size_t)ML*EV];
#define WTOT 14942208
__device__ __align__(16) fp16 g_wh[WTOT];
__device__ __align__(16) fp16 g_wl[WTOT];   // only patch region used (2-pass)

// ---------------- helpers -----------------------------------------------------
__device__ __forceinline__ float geluf(float v) {
    return 0.5f * v * (1.f + erff(v * 0.70710678118654752f));
}
__device__ __forceinline__ uint32_t s2u(const void* p) {
    uint32_t a;
    asm("{ .reg .u64 t; cvta.to.shared.u64 t, %1; cvt.u32.u64 %0, t; }" : "=r"(a) : "l"(p));
    return a;
}
__device__ __forceinline__ void cpa16(uint32_t saddr, const void* g, int sz) {
    asm volatile("cp.async.cg.shared.global [%0], [%1], 16, %2;"
                 :: "r"(saddr), "l"(g), "r"(sz) : "memory");
}
__device__ __forceinline__ void mma16816(float* d, const uint32_t* a, uint32_t b0, uint32_t b1) {
    asm volatile("mma.sync.aligned.m16n8k16.row.col.f32.f16.f16.f32 "
                 "{%0,%1,%2,%3},{%4,%5,%6,%7},{%8,%9},{%0,%1,%2,%3};"
                 : "+f"(d[0]), "+f"(d[1]), "+f"(d[2]), "+f"(d[3])
                 : "r"(a[0]), "r"(a[1]), "r"(a[2]), "r"(a[3]), "r"(b0), "r"(b1));
}
__device__ __forceinline__ void ldsm4(uint32_t& r0, uint32_t& r1, uint32_t& r2, uint32_t& r3,
                                      uint32_t saddr) {
    asm volatile("ldmatrix.sync.aligned.m8n8.x4.shared.b16 {%0,%1,%2,%3}, [%4];"
                 : "=r"(r0), "=r"(r1), "=r"(r2), "=r"(r3) : "r"(saddr));
}
__device__ __forceinline__ void ldsm4t(uint32_t& r0, uint32_t& r1, uint32_t& r2, uint32_t& r3,
                                       uint32_t saddr) {
    asm volatile("ldmatrix.sync.aligned.m8n8.x4.trans.shared.b16 {%0,%1,%2,%3}, [%4];"
                 : "=r"(r0), "=r"(r1), "=r"(r2), "=r"(r3) : "r"(saddr));
}
__device__ __forceinline__ uint32_t h2u(float c0, float c1) {
    __half2 h = __floats2half2_rn(c0, c1);
    return *(uint32_t*)&h;
}
__device__ __forceinline__ uint32_t ex2h2(float c0, float c1) {
    uint32_t x = h2u(c0, c1), r;
    asm("ex2.approx.f16x2 %0, %1;" : "=r"(r) : "r"(x));
    return r;
}

// ---------------- fp16 tensor-core GEMM (mma.sync + ldmatrix) -----------------
// NPASS==1: K-chunk 64, 3-stage pipeline. NPASS==2: K-chunk 32, 2-stage.
template<int NPASS> struct HGC {
    static constexpr int KCH  = (NPASS == 1) ? 64 : 32;
    static constexpr int STR  = KCH + 8;
    static constexpr int MATH = 128 * STR;
    static constexpr int BUFH = (1 + NPASS) * MATH;
    static constexpr int NST  = (NPASS == 1) ? 3 : 2;
    static constexpr int SMEM = NST * BUFH * 2;
};

template<int ACT, int OUT, int NPASS, int QSCALE, int POSE>
__global__ void __launch_bounds__(256, 2)
hgemm(const fp16* __restrict__ A, const fp16* __restrict__ Bh, const fp16* __restrict__ Bl,
      const float* __restrict__ bias, const float* __restrict__ res,
      float* __restrict__ C, fp16* __restrict__ Cf, int M, int N, int K)
{
    constexpr int NMAT = 1 + NPASS;
    constexpr int KCH  = HGC<NPASS>::KCH;
    constexpr int STR  = HGC<NPASS>::STR;
    constexpr int MATH = HGC<NPASS>::MATH;
    constexpr int BUFH = HGC<NPASS>::BUFH;
    constexpr int NST  = HGC<NPASS>::NST;
    constexpr int GPR  = KCH / 8;
    constexpr int ITER = 128 * GPR / 256;
    extern __shared__ fp16 sm[];
    const int tid = threadIdx.x, wid = tid >> 5, lane = tid & 31;
    const int m0 = blockIdx.x * 128, n0 = blockIdx.y * 128;
    const int g = lane >> 2, t = lane & 3;
    const int wm0 = (wid >> 1) * 32, wn0 = (wid & 1) * 64;
    const uint32_t smbase = s2u(sm);
    const fp16* srcs[3] = {A, Bh, Bl};
    const int arow8 = ((lane >> 3) & 1) * 8 + (lane & 7);
    const int acol8 = (lane >> 4) * 8;
    const int bnf   = lane >> 4;
    const int brow  = lane & 7;
    const int bcol8 = ((lane >> 3) & 1) * 8;

    float acc[2][8][4];
    #pragma unroll
    for (int i = 0; i < 2; ++i)
        #pragma unroll
        for (int j = 0; j < 8; ++j)
            #pragma unroll
            for (int u = 0; u < 4; ++u) acc[i][j][u] = 0.f;

    const int KC = K / KCH;

    auto issue = [&](int c, int buf) {
        int k0 = c * KCH;
        #pragma unroll
        for (int mat = 0; mat < NMAT; ++mat) {
            #pragma unroll
            for (int it = 0; it < ITER; ++it) {
                int idx = it * 256 + tid;
                int row = idx / GPR, q8 = idx % GPR;
                int grow = (mat == 0) ? (m0 + row) : (n0 + row);
                bool ok = (mat > 0) || (grow < M);
                const fp16* gp = ok ? (srcs[mat] + (size_t)grow * K + k0 + q8 * 8) : srcs[mat];
                uint32_t sa = smbase + (uint32_t)(buf * BUFH + mat * MATH + row * STR + q8 * 8) * 2;
                cpa16(sa, gp, ok ? 16 : 0);
            }
        }
        asm volatile("cp.async.commit_group;" ::: "memory");
    };

    issue(0, 0);
    if (NST == 3 && KC > 1) issue(1, 1);
    int bufc = 0;
    for (int c = 0; c < KC; ++c) {
        if (NST == 3) {
            if (c + 2 < KC) {
                int nb = bufc + 2; if (nb >= 3) nb -= 3;
                issue(c + 2, nb);
                asm volatile("cp.async.wait_group 2;" ::: "memory");
            } else if (c + 1 < KC) {
                asm volatile("cp.async.wait_group 1;" ::: "memory");
            } else {
                asm volatile("cp.async.wait_group 0;" ::: "memory");
            }
        } else {
            if (c + 1 < KC) {
                issue(c + 1, bufc ^ 1);
                asm volatile("cp.async.wait_group 1;" ::: "memory");
            } else {
                asm volatile("cp.async.wait_group 0;" ::: "memory");
            }
        }
        __syncthreads();
        const uint32_t bufoff = (uint32_t)bufc * BUFH;
        #pragma unroll
        for (int ks = 0; ks < KCH; ks += 16) {
            uint32_t afr[2][4];
            #pragma unroll
            for (int mf = 0; mf < 2; ++mf) {
                uint32_t addr = smbase + (bufoff + (uint32_t)((wm0 + mf * 16 + arow8) * STR + ks + acol8)) * 2;
                ldsm4(afr[mf][0], afr[mf][1], afr[mf][2], afr[mf][3], addr);
            }
            #pragma unroll
            for (int p = 0; p < 8; p += 2) {
                uint32_t b0, b1, b2, b3;
                uint32_t baddr = smbase + (bufoff + (uint32_t)(MATH + (wn0 + (p + bnf) * 8 + brow) * STR + ks + bcol8)) * 2;
                ldsm4(b0, b1, b2, b3, baddr);
                #pragma unroll
                for (int mf = 0; mf < 2; ++mf) {
                    mma16816(acc[mf][p],     afr[mf], b0, b1);
                    mma16816(acc[mf][p + 1], afr[mf], b2, b3);
                }
                if (NPASS == 2) {
                    uint32_t l0, l1, l2, l3;
                    ldsm4(l0, l1, l2, l3, baddr + MATH * 2);
                    #pragma unroll
                    for (int mf = 0; mf < 2; ++mf) {
                        mma16816(acc[mf][p],     afr[mf], l0, l1);
                        mma16816(acc[mf][p + 1], afr[mf], l2, l3);
                    }
                }
            }
        }
        bufc = (bufc + 1 == NST) ? 0 : bufc + 1;
        __syncthreads();
    }

    #pragma unroll
    for (int mf = 0; mf < 2; ++mf) {
        #pragma unroll
        for (int rr = 0; rr < 2; ++rr) {
            int row = m0 + wm0 + mf * 16 + g + rr * 8;
            if (row >= M) continue;
            #pragma unroll
            for (int nf = 0; nf < 8; ++nf) {
                int col = n0 + wn0 + nf * 8 + 2 * t;
                float c0 = acc[mf][nf][rr * 2 + 0] + bias[col];
                float c1 = acc[mf][nf][rr * 2 + 1] + bias[col + 1];
                if (ACT) { c0 = geluf(c0); c1 = geluf(c1); }
                if (QSCALE && col < 768) { c0 *= 0.125f; c1 *= 0.125f; }
                if (OUT == 1) {
                    __half2 h = __floats2half2_rn(c0, c1);
                    *(__half2*)(Cf + (size_t)row * N + col) = h;
                } else if (POSE) {
                    int bI = row / NP, pI = row - bI * NP;
                    size_t hrow = (size_t)bI * LV + 1 + pI;
                    c0 += res[(size_t)(1 + pI) * EV + col];
                    c1 += res[(size_t)(1 + pI) * EV + col + 1];
                    *(float2*)(C + hrow * EV + col) = make_float2(c0, c1);
                } else {
                    if (res) {
                        c0 += res[(size_t)row * N + col];
                        c1 += res[(size_t)row * N + col + 1];
                    }
                    *(float2*)(C + (size_t)row * N + col) = make_float2(c0, c1);
                }
            }
        }
    }
}

// ---------------- fused flash attention — 64-key chunks, occupancy 2 ---------
#define FA_STR 72
#define FA_Q 0
#define FA_K(b)  (9216 + (b)*4608)
#define FA_V(b)  (18432 + (b)*4608)
#define FA_SMEM (27648*2)

__global__ void __launch_bounds__(256, 2)
fattn(const fp16* __restrict__ qkv, int layer_unused)
{
    const int wsA[5] = {768, 1536, 3072, 6144, 12288};
    const int rsA[5] = {1, 2, 4, 8, 16};
    const int gsA[5] = {12, 6, 3, 2, 1};
    const int nsA[5] = {5, 3, 2, 1, 1};
    const int ubA[5] = {0, 120, 192, 240, 264};

    extern __shared__ fp16 sm[];
    const int tid = threadIdx.x, wid = tid >> 5, lane = tid & 31;
    const int g = lane >> 2, t = lane & 3;
    int gu = blockIdx.y;
    int br = (gu >= 264) ? 4 : (gu >= 240) ? 3 : (gu >= 192) ? 2 : (gu >= 120) ? 1 : 0;
    int z = gu - ubA[br];
    int w = wsA[br], r = rsA[br], gsz = gsA[br], n = nsA[br];
    int hd = z % HH;
    int seg = (z / HH) % n;
    int bb_ = z / (HH * n);
    int off = hd / gsz;
    int m0 = blockIdx.x * 128;
    const uint32_t smb = s2u(sm);
    const int arow8 = ((lane >> 3) & 1) * 8 + (lane & 7);
    const int acol8 = (lane >> 4) * 8;
    const int bnf   = lane >> 4;
    const int brow  = lane & 7;
    const int bcol8 = ((lane >> 3) & 1) * 8;
    const int vrow  = lane & 15;
    const int vcol  = lane >> 4;
    const fp16* q = qkv;
    const fp16* k = qkv + 768;
    const fp16* v = qkv + 1536;

    auto kv_issue = [&](int kt, int buf) {
        int n0 = kt * 64;
        #pragma unroll
        for (int it = 0; it < 2; ++it) {
            int idx = it * 256 + tid;
            int row = idx >> 3, q8 = idx & 7;
            int pos = seg * w + (n0 + row) * r + off;
            bool ok = pos < LV;
            const fp16* gpk = ok ? (k + ((size_t)(bb_ * LV) + pos) * QKVS + hd * DHv + q8 * 8) : k;
            cpa16(smb + (uint32_t)(FA_K(buf) + row * FA_STR + q8 * 8) * 2, gpk, ok ? 16 : 0);
            const fp16* gpv = ok ? (v + ((size_t)(bb_ * LV) + pos) * QKVS + hd * DHv + q8 * 8) : v;
            cpa16(smb + (uint32_t)(FA_V(buf) + row * FA_STR + q8 * 8) * 2, gpv, ok ? 16 : 0);
        }
        asm volatile("cp.async.commit_group;" ::: "memory");
    };

    #pragma unroll
    for (int it = 0; it < 4; ++it) {
        int idx = it * 256 + tid;
        int row = idx >> 3, q8 = idx & 7;
        int pos = seg * w + (m0 + row) * r + off;
        bool ok = pos < LV;
        const fp16* gp = ok ? (q + ((size_t)(bb_ * LV) + pos) * QKVS + hd * DHv + q8 * 8) : q;
        cpa16(smb + (uint32_t)(FA_Q + row * FA_STR + q8 * 8) * 2, gp, ok ? 16 : 0);
    }
    kv_issue(0, 0);
    asm volatile("cp.async.wait_group 0;" ::: "memory");
    __syncthreads();

    uint32_t qfr[4][4];
    #pragma unroll
    for (int k4 = 0; k4 < 4; ++k4) {
        uint32_t addr = smb + (uint32_t)(FA_Q + (wid * 16 + arow8) * FA_STR + k4 * 16 + acol8) * 2;
        ldsm4(qfr[k4][0], qfr[k4][1], qfr[k4][2], qfr[k4][3], addr);
    }

    float m_[2] = {-1e30f, -1e30f};
    float l_[2] = {0.f, 0.f};
    float acco[8][4];
    #pragma unroll
    for (int j = 0; j < 8; ++j)
        #pragma unroll
        for (int u = 0; u < 4; ++u) acco[j][u] = 0.f;

    for (int kt = 0; kt < 12; ++kt) {
        int buf = kt & 1;
        if (kt < 11) kv_issue(kt + 1, buf ^ 1);

        float accs[8][4];
        #pragma unroll
        for (int j = 0; j < 8; ++j)
            #pragma unroll
            for (int u = 0; u < 4; ++u) accs[j][u] = 0.f;
        #pragma unroll
        for (int k4 = 0; k4 < 4; ++k4) {
            #pragma unroll
            for (int p = 0; p < 8; p += 2) {
                uint32_t b0, b1, b2, b3;
                uint32_t addr = smb + (uint32_t)(FA_K(buf) + ((p + bnf) * 8 + brow) * FA_STR + k4 * 16 + bcol8) * 2;
                ldsm4(b0, b1, b2, b3, addr);
                mma16816(accs[p],     qfr[k4], b0, b1);
                mma16816(accs[p + 1], qfr[k4], b2, b3);
            }
        }

        float mx0 = -1e30f, mx1 = -1e30f;
        #pragma unroll
        for (int nf = 0; nf < 8; ++nf) {
            mx0 = fmaxf(mx0, fmaxf(accs[nf][0], accs[nf][1]));
            mx1 = fmaxf(mx1, fmaxf(accs[nf][2], accs[nf][3]));
        }
        mx0 = fmaxf(mx0, __shfl_xor_sync(0xffffffffu, mx0, 1));
        mx0 = fmaxf(mx0, __shfl_xor_sync(0xffffffffu, mx0, 2));
        mx1 = fmaxf(mx1, __shfl_xor_sync(0xffffffffu, mx1, 1));
        mx1 = fmaxf(mx1, __shfl_xor_sync(0xffffffffu, mx1, 2));
        float mn0 = fmaxf(m_[0], mx0), mn1 = fmaxf(m_[1], mx1);
        float mnl0 = mn0 * LOG2E, mnl1 = mn1 * LOG2E;
        uint32_t pfr[8][2];
        float sum0 = 0.f, sum1 = 0.f;
        #pragma unroll
        for (int nf = 0; nf < 8; ++nf) {
            float t0 = fmaf(accs[nf][0], LOG2E, -mnl0);
            float t1 = fmaf(accs[nf][1], LOG2E, -mnl0);
            float t2 = fmaf(accs[nf][2], LOG2E, -mnl1);
            float t3 = fmaf(accs[nf][3], LOG2E, -mnl1);
            pfr[nf][0] = ex2h2(t0, t1);
            pfr[nf][1] = ex2h2(t2, t3);
            float2 f0 = __half22float2(*(__half2*)&pfr[nf][0]);
            float2 f1 = __half22float2(*(__half2*)&pfr[nf][1]);
            sum0 += f0.x + f0.y;
            sum1 += f1.x + f1.y;
        }
        sum0 += __shfl_xor_sync(0xffffffffu, sum0, 1);
        sum0 += __shfl_xor_sync(0xffffffffu, sum0, 2);
        sum1 += __shfl_xor_sync(0xffffffffu, sum1, 1);
        sum1 += __shfl_xor_sync(0xffffffffu, sum1, 2);
        float sc0 = __expf(m_[0] - mn0), sc1 = __expf(m_[1] - mn1);
        l_[0] = l_[0] * sc0 + sum0;
        l_[1] = l_[1] * sc1 + sum1;
        m_[0] = mn0; m_[1] = mn1;
        #pragma unroll
        for (int nf = 0; nf < 8; ++nf) {
            acco[nf][0] *= sc0; acco[nf][1] *= sc0;
            acco[nf][2] *= sc1; acco[nf][3] *= sc1;
        }

        #pragma unroll
        for (int kb = 0; kb < 4; ++kb) {
            uint32_t a[4] = {pfr[2*kb][0], pfr[2*kb][1], pfr[2*kb+1][0], pfr[2*kb+1][1]};
            #pragma unroll
            for (int p = 0; p < 8; p += 2) {
                uint32_t b0, b1, b2, b3;
                uint32_t addr = smb + (uint32_t)(FA_V(buf) + (kb * 16 + vrow) * FA_STR + (p + vcol) * 8) * 2;
                ldsm4t(b0, b1, b2, b3, addr);
                mma16816(acco[p],     a, b0, b1);
                mma16816(acco[p + 1], a, b2, b3);
            }
        }

        if (kt < 11) {
            asm volatile("cp.async.wait_group 0;" ::: "memory");
            __syncthreads();
        }
    }

    float inv0 = 1.f / l_[0], inv1 = 1.f / l_[1];
    int row0 = m0 + wid * 16 + g;
    int row1 = row0 + 8;
    fp16* Op = g_obr + (size_t)gu * 49152;
    #pragma unroll
    for (int nf = 0; nf < 8; ++nf) {
        int col = nf * 8 + 2 * t;
        *(__half2*)(Op + (size_t)row0 * 64 + col) = __floats2half2_rn(acco[nf][0] * inv0, acco[nf][1] * inv0);
        *(__half2*)(Op + (size_t)row1 * 64 + col) = __floats2half2_rn(acco[nf][2] * inv1, acco[nf][3] * inv1);
    }
    if (t == 0) {
        g_lse[(size_t)gu * 768 + row0] = m_[0] + logf(l_[0]);
        g_lse[(size_t)gu * 768 + row1] = m_[1] + logf(l_[1]);
    }
}

// ---------------- misc kernels ------------------------------------------------
__global__ void im2col_half(const float* __restrict__ x) {
    int idx = blockIdx.x * 256 + threadIdx.x;
    if (idx >= BV * NP * 1024) return;
    int kk = idx & 1023;
    int p  = (idx >> 10) % NP;
    int b  = (idx >> 10) / NP;
    int pw_ = kk & 15, ph_ = (kk >> 4) & 15, pd_ = kk >> 8;
    int bz = p & 15, by = (p >> 4) & 15, bx = p >> 8;
    float v = x[(((size_t)b * 48 + bx * 4 + pd_) * 256 + by * 16 + ph_) * 256 + bz * 16 + pw_];
    g_col[idx] = __float2half_rn(v);
}

__global__ void cls_kernel(const float* __restrict__ cls, const float* __restrict__ pos) {
    int e = blockIdx.x * 256 + threadIdx.x;
    if (e >= EV) return;
    float v = cls[e] + pos[e];
    g_h[e] = v;
    g_h[(size_t)LV * EV + e] = v;
}

// warp-per-row layernorm: 8 rows per 256-thread block
template<int HOUT>
__global__ void layernorm_kernel(const float* __restrict__ x, const float* __restrict__ g,
                                 const float* __restrict__ bta, float* __restrict__ y,
                                 fp16* __restrict__ yf)
{
    int row = blockIdx.x * 8 + (threadIdx.x >> 5);
    if (row >= ML) return;
    int lane = threadIdx.x & 31;
    const float4* xr = (const float4*)(x + (size_t)row * EV);
    float4 v[6];
    float s = 0.f, s2 = 0.f;
    #pragma unroll
    for (int i = 0; i < 6; ++i) {
        v[i] = xr[lane + 32 * i];
        s  += v[i].x + v[i].y + v[i].z + v[i].w;
        s2 += v[i].x*v[i].x + v[i].y*v[i].y + v[i].z*v[i].z + v[i].w*v[i].w;
    }
    #pragma unroll
    for (int o = 16; o; o >>= 1) {
        s  += __shfl_xor_sync(0xffffffffu, s, o);
        s2 += __shfl_xor_sync(0xffffffffu, s2, o);
    }
    float mu = s * (1.f / 768.f);
    float var = s2 * (1.f / 768.f) - mu * mu;
    float inv = rsqrtf(var + 1e-5f);
    #pragma unroll
    for (int i = 0; i < 6; ++i) {
        int j = lane + 32 * i;
        float4 gg = ((const float4*)g)[j];
        float4 bb = ((const float4*)bta)[j];
        float c0 = (v[i].x - mu) * inv * gg.x + bb.x;
        float c1 = (v[i].y - mu) * inv * gg.y + bb.y;
        float c2 = (v[i].z - mu) * inv * gg.z + bb.z;
        float c3 = (v[i].w - mu) * inv * gg.w + bb.w;
        if (HOUT) {
            __half2* yp = (__half2*)(yf + (size_t)row * EV + 4 * j);
            yp[0] = __floats2half2_rn(c0, c1);
            yp[1] = __floats2half2_rn(c2, c3);
        } else {
            ((float4*)(y + (size_t)row * EV))[j] = make_float4(c0, c1, c2, c3);
        }
    }
}

// final layernorm: only the 2 cls rows are consumed by the head
__global__ void layernorm_cls(const float* __restrict__ x, const float* __restrict__ g,
                              const float* __restrict__ bta, float* __restrict__ y)
{
    int b = threadIdx.x >> 5;
    int lane = threadIdx.x & 31;
    if (b >= BV) return;
    const float4* xr = (const float4*)(x + (size_t)b * LV * EV);
    float4 v[6];
    float s = 0.f, s2 = 0.f;
    #pragma unroll
    for (int i = 0; i < 6; ++i) {
        v[i] = xr[lane + 32 * i];
        s  += v[i].x + v[i].y + v[i].z + v[i].w;
        s2 += v[i].x*v[i].x + v[i].y*v[i].y + v[i].z*v[i].z + v[i].w*v[i].w;
    }
    #pragma unroll
    for (int o = 16; o; o >>= 1) {
        s  += __shfl_xor_sync(0xffffffffu, s, o);
        s2 += __shfl_xor_sync(0xffffffffu, s2, o);
    }
    float mu = s * (1.f / 768.f);
    float var = s2 * (1.f / 768.f) - mu * mu;
    float inv = rsqrtf(var + 1e-5f);
    #pragma unroll
    for (int i = 0; i < 6; ++i) {
        int j = lane + 32 * i;
        float4 gg = ((const float4*)g)[j];
        float4 bb = ((const float4*)bta)[j];
        ((float4*)(y + (size_t)b * EV))[j] = make_float4(
            (v[i].x - mu) * inv * gg.x + bb.x,
            (v[i].y - mu) * inv * gg.y + bb.y,
            (v[i].z - mu) * inv * gg.z + bb.z,
            (v[i].w - mu) * inv * gg.w + bb.w);
    }
}

__global__ void combine_kernel()
{
    int idx = blockIdx.x * 4 + (threadIdx.x >> 6);
    int d = threadIdx.x & 63;
    int hd = idx % HH;
    int p = (idx / HH) % LV;
    int b = idx / (HH * LV);
    if (b >= BV) return;
    const int ws[5] = {768, 1536, 3072, 6144, 12288};
    const int rs[5] = {1, 2, 4, 8, 16};
    const int gs[5] = {12, 6, 3, 2, 1};
    const int ns[5] = {5, 3, 2, 1, 1};
    const int ub[5] = {0, 120, 192, 240, 264};
    float lses[5];
    size_t oix[5];
    bool cov[5];
    float mx = -1e30f;
    #pragma unroll
    for (int br = 0; br < 5; ++br) {
        int seg = p / ws[br];
        int jj = p - seg * ws[br];
        int off = hd / gs[br];
        int rr = jj & (rs[br] - 1);
        cov[br] = (rr == off);
        if (cov[br]) {
            int j = jj / rs[br];
            int unit = ub[br] + (b * ns[br] + seg) * HH + hd;
            lses[br] = g_lse[(size_t)unit * 768 + j];
            oix[br] = (size_t)unit * 49152 + (size_t)j * 64;
            mx = fmaxf(mx, lses[br]);
        }
    }
    float sw = 0.f, out = 0.f;
    #pragma unroll
    for (int br = 0; br < 5; ++br) {
        if (cov[br]) {
            float wgt = __expf(lses[br] - mx);
            sw += wgt;
            out += wgt * __half2float(g_obr[oix[br] + d]);
        }
    }
    g_o[((size_t)(b * LV + p)) * EV + hd * DHv + d] = __float2half_rn(out / sw);
}

__global__ void head_init(const float* __restrict__ bias, float* __restrict__ out) {
    int i = blockIdx.x * 256 + threadIdx.x;
    if (i >= BV * 1000) return;
    out[i] = bias[i % 1000];
}

// split-e head GEMV: grid (8, 6, BV), block 128; atomicAdd partials
__global__ void head_kernel(const float* __restrict__ hn, const float* __restrict__ W,
                            float* __restrict__ out)
{
    int nidx = blockIdx.x * 128 + threadIdx.x;
    int ec = blockIdx.y * 128;
    int b = blockIdx.z;
    if (nidx >= 1000) return;
    const float* row = hn + (size_t)b * EV + ec;
    const float* Wp = W + (size_t)ec * 1000 + nidx;
    float acc = 0.f;
    #pragma unroll 4
    for (int e = 0; e < 128; ++e) acc = fmaf(row[e], Wp[(size_t)e * 1000], acc);
    atomicAdd(&out[b * 1000 + nidx], acc);
}

__global__ void transT_all(const float* __restrict__ wq, const float* __restrict__ wk,
                           const float* __restrict__ wv, const float* __restrict__ wo,
                           const float* __restrict__ w1, const float* __restrict__ w2,
                           fp16* __restrict__ dst)
{
    int tile = blockIdx.x;
    const float* src;
    int K, N, kb, nb;
    size_t doff;
    if (tile < 2304) {
        int wsel = tile / 576, tt = tile % 576;
        src = (wsel == 0) ? wq : (wsel == 1) ? wk : (wsel == 2) ? wv : wo;
        K = 768; N = 768; doff = (size_t)wsel * 589824;
        kb = (tt % 24) * 32; nb = (tt / 24) * 32;
    } else if (tile < 4608) {
        int tt = tile - 2304;
        src = w1; K = 768; N = 3072; doff = 2359296;
        kb = (tt % 24) * 32; nb = (tt / 24) * 32;
    } else {
        int tt = tile - 4608;
        src = w2; K = 3072; N = 768; doff = 4718592;
        kb = (tt % 96) * 32; nb = (tt / 96) * 32;
    }
    __shared__ float t[32][33];
    int x = threadIdx.x, y = threadIdx.y;
    #pragma unroll
    for (int i = 0; i < 32; i += 8)
        t[y + i][x] = src[(size_t)(kb + y + i) * N + nb + x];
    __syncthreads();
    #pragma unroll
    for (int i = 0; i < 32; i += 8)
        dst[doff + (size_t)(nb + y + i) * K + kb + x] = __float2half_rn(t[x][y + i]);
}

__global__ void split_copy(const float* __restrict__ s, fp16* __restrict__ oh,
                           fp16* __restrict__ ol, long n)
{
    long i = ((long)blockIdx.x * 256 + threadIdx.x) * 4;
    if (i >= n) return;
    float4 v = *(const float4*)(s + i);
    float vv[4] = {v.x, v.y, v.z, v.w};
    #pragma unroll
    for (int u = 0; u < 4; ++u) {
        fp16 h = __float2half_rn(vv[u]);
        oh[i + u] = h;
        ol[i + u] = __float2half_rn(vv[u] - __half2float(h));
    }
}

__global__ void pack_bias(const float* __restrict__ bq, const float* __restrict__ bk,
                          const float* __restrict__ bv)
{
    int i = blockIdx.x * 256 + threadIdx.x;
    if (i >= 2 * QKVS) return;
    int l = i / QKVS, e = i % QKVS;
    float v;
    if (e < 768)       v = bq[l * EV + e];
    else if (e < 1536) v = bk[l * EV + e - 768];
    else               v = bv[l * EV + e - 1536];
    g_bqkv[i] = v;
}

// ---------------- host orchestration ------------------------------------------
extern "C" void kernel_launch(void* const* d_in, const int* in_sizes, int n_in,
                              void* d_out, int out_size)
{
    (void)in_sizes; (void)n_in; (void)out_size;
    const float* x        = (const float*)d_in[0];
    const float* patch_w  = (const float*)d_in[1];
    const float* patch_b  = (const float*)d_in[2];
    const float* cls_tok  = (const float*)d_in[3];
    const float* pos_emb  = (const float*)d_in[4];
    const float* ln1_g    = (const float*)d_in[5];
    const float* ln1_b    = (const float*)d_in[6];
    const float* wq       = (const float*)d_in[7];
    const float* bq       = (const float*)d_in[8];
    const float* wk       = (const float*)d_in[9];
    const float* bk       = (const float*)d_in[10];
    const float* wv       = (const float*)d_in[11];
    const float* bv_      = (const float*)d_in[12];
    const float* wo       = (const float*)d_in[13];
    const float* bo       = (const float*)d_in[14];
    const float* ln2_g    = (const float*)d_in[15];
    const float* ln2_b    = (const float*)d_in[16];
    const float* w1       = (const float*)d_in[17];
    const float* b1       = (const float*)d_in[18];
    const float* w2       = (const float*)d_in[19];
    const float* b2       = (const float*)d_in[20];
    const float* normf_g  = (const float*)d_in[21];
    const float* normf_b  = (const float*)d_in[22];
    const float* head_w   = (const float*)d_in[23];
    const float* head_b   = (const float*)d_in[24];
    float* out = (float*)d_out;

    float *p_h, *p_hn, *p_bqkv;
    fp16 *p_col, *p_x, *p_qkv, *p_m1, *p_o, *p_wh, *p_wl;
    cudaGetSymbolAddress((void**)&p_h, g_h);
    cudaGetSymbolAddress((void**)&p_hn, g_hn);
    cudaGetSymbolAddress((void**)&p_bqkv, g_bqkv);
    cudaGetSymbolAddress((void**)&p_col, g_col);
    cudaGetSymbolAddress((void**)&p_x, g_x);
    cudaGetSymbolAddress((void**)&p_qkv, g_qkv);
    cudaGetSymbolAddress((void**)&p_m1, g_m1);
    cudaGetSymbolAddress((void**)&p_o, g_o);
    cudaGetSymbolAddress((void**)&p_wh, g_wh);
    cudaGetSymbolAddress((void**)&p_wl, g_wl);

    const int SM2 = HGC<2>::SMEM;
    const int SM1 = HGC<1>::SMEM;
    cudaFuncSetAttribute(hgemm<0,0,2,0,1>, cudaFuncAttributeMaxDynamicSharedMemorySize, SM2);
    cudaFuncSetAttribute(hgemm<0,1,1,1,0>, cudaFuncAttributeMaxDynamicSharedMemorySize, SM1);
    cudaFuncSetAttribute(hgemm<0,0,1,0,0>, cudaFuncAttributeMaxDynamicSharedMemorySize, SM1);
    cudaFuncSetAttribute(hgemm<1,1,1,0,0>, cudaFuncAttributeMaxDynamicSharedMemorySize, SM1);
    cudaFuncSetAttribute(fattn, cudaFuncAttributeMaxDynamicSharedMemorySize, FA_SMEM);

    // ---- prep -------------------------------------------------------------------
    const size_t LSZ = 7077888;
    dim3 blk(32, 8);
    {
        long n = 786432;
        split_copy<<<(int)((n/4 + 255) / 256), 256>>>(patch_w, p_wh, p_wl, n);
    }
    im2col_half<<<(BV * NP * 1024 + 255) / 256, 256>>>(x);
    pack_bias<<<(2 * QKVS + 255) / 256, 256>>>(bq, bk, bv_);
    transT_all<<<6912, blk>>>(wq, wk, wv, wo, w1, w2, p_wh + 786432);
    // patch embed fused with pos-embed scatter into g_h
    hgemm<0,0,2,0,1><<<dim3(48, 6), 256, SM2>>>(p_col, p_wh, p_wl,
                                                patch_b, pos_emb, p_h, nullptr,
                                                BV * NP, EV, 1024);
    transT_all<<<6912, blk>>>(wq + 589824, wk + 589824, wv + 589824, wo + 589824,
                              w1 + 2359296, w2 + 2359296, p_wh + 786432 + LSZ);
    cls_kernel<<<3, 256>>>(cls_tok, pos_emb);

    dim3 gEEt(49, 6);
    dim3 gQKV(49, 18);
    dim3 gE4t(49, 24);
    const int LNG = (ML + 7) / 8;

    for (int layer = 0; layer < 2; ++layer) {
        size_t base = 786432 + (size_t)layer * LSZ;
        size_t oE  = (size_t)layer * EV;
        size_t o4  = (size_t)layer * 3072;

        layernorm_kernel<1><<<LNG, 256>>>(p_h, ln1_g + oE, ln1_b + oE, nullptr, p_x);
        hgemm<0,1,1,1,0><<<gQKV, 256, SM1>>>(p_x, p_wh + base, p_wl,
                                             p_bqkv + layer * QKVS, nullptr, nullptr, p_qkv,
                                             ML, QKVS, EV);

        fattn<<<dim3(6, 288), 256, FA_SMEM>>>(p_qkv, layer);
        combine_kernel<<<(BV * LV * HH + 3) / 4, 256>>>();

        hgemm<0,0,1,0,0><<<gEEt, 256, SM1>>>(p_o, p_wh + base + 1769472, p_wl, bo + oE, p_h, p_h, nullptr, ML, EV, EV);

        layernorm_kernel<1><<<LNG, 256>>>(p_h, ln2_g + oE, ln2_b + oE, nullptr, p_x);
        hgemm<1,1,1,0,0><<<gE4t, 256, SM1>>>(p_x, p_wh + base + 2359296, p_wl, b1 + o4, nullptr, nullptr, p_m1, ML, 3072, EV);
        hgemm<0,0,1,0,0><<<gEEt, 256, SM1>>>(p_m1, p_wh + base + 4718592, p_wl, b2 + oE, p_h, p_h, nullptr, ML, EV, 3072);
    }

    layernorm_cls<<<1, 64>>>(p_h, normf_g, normf_b, p_hn);
    head_init<<<(BV * 1000 + 255) / 256, 256>>>(head_b, out);
    head_kernel<<<dim3(8, 6, BV), 128>>>(p_hn, head_w, out);
}